// round 13
// baseline (speedup 1.0000x reference)
#include <cuda_runtime.h>
#include <cuda_fp16.h>
#include <stdint.h>
#include <math.h>

#define NN   8192
#define EMB  128
#define KL   3
#define NKE  (KL * EMB)   // 384

// ---------------- persistent scratch (no allocations allowed) ----------------
__device__ __align__(16) __half g_Ah [(size_t)NN * NN];   // A row-major fp16
__device__ __align__(16) __half g_ATh[(size_t)NN * NN];   // A^T fp16
__device__ __align__(16) __half g_Wph[(size_t)NKE * NN];  // Wp^T fp16
__device__ __align__(16) __half g_Wqh[(size_t)NKE * NN];  // Wq^T fp16
__device__ __align__(16) __half g_dech[(size_t)NN * EMB];
__device__ __align__(16) __half g_qh  [(size_t)NN * EMB];
__device__ float g_Dout[NN];
__device__ float g_Din [NN];

// ---------------- helpers ----------------
__device__ __forceinline__ void cp16(uint32_t dst_smem, const void* src) {
    asm volatile("cp.async.ca.shared.global [%0], [%1], 16;\n"
                 :: "r"(dst_smem), "l"(src));
}
__device__ __forceinline__ void mma16816(float* c, const uint32_t* a, const uint32_t* b) {
    asm volatile(
        "mma.sync.aligned.m16n8k16.row.col.f32.f16.f16.f32 "
        "{%0,%1,%2,%3}, {%4,%5,%6,%7}, {%8,%9}, {%0,%1,%2,%3};\n"
        : "+f"(c[0]), "+f"(c[1]), "+f"(c[2]), "+f"(c[3])
        : "r"(a[0]), "r"(a[1]), "r"(a[2]), "r"(a[3]), "r"(b[0]), "r"(b[1]));
}
__device__ __forceinline__ void ldsm4(uint32_t* r, uint32_t addr) {
    asm volatile("ldmatrix.sync.aligned.m8n8.x4.shared.b16 {%0,%1,%2,%3}, [%4];"
                 : "=r"(r[0]), "=r"(r[1]), "=r"(r[2]), "=r"(r[3]) : "r"(addr));
}
__device__ __forceinline__ uint32_t smem_u32(const void* p) {
    return (uint32_t)__cvta_generic_to_shared(p);
}
__device__ __forceinline__ float fast_lg2(float x) {
    float y; asm("lg2.approx.f32 %0, %1;" : "=f"(y) : "f"(x)); return y;
}
__device__ __forceinline__ float fast_ex2(float x) {
    float y; asm("ex2.approx.f32 %0, %1;" : "=f"(y) : "f"(x)); return y;
}

__global__ void zero_deg_kernel() {
    int i = blockIdx.x * blockDim.x + threadIdx.x;
    if (i < NN) { g_Dout[i] = 0.0f; g_Din[i] = 0.0f; }
}

// ---------------- prep: A -> fp16 (row-major + transposed) + degrees ----------------
__global__ void __launch_bounds__(256) prep_kernel(const float* __restrict__ A) {
    __shared__ float tile[64][65];
    const int bi = blockIdx.y * 64;
    const int bj = blockIdx.x * 64;
    const int tid = threadIdx.x;
    const int r  = tid >> 2;
    const int cs = tid & 3;

    const float* src = A + (size_t)(bi + r) * NN + bj + cs * 16;
    float v[16];
    #pragma unroll
    for (int u = 0; u < 4; u++) {
        float4 f = *(const float4*)(src + u * 4);
        v[u*4+0] = f.x; v[u*4+1] = f.y; v[u*4+2] = f.z; v[u*4+3] = f.w;
    }
    __align__(16) __half h[16];
    float rs = 0.f;
    #pragma unroll
    for (int u = 0; u < 16; u++) {
        h[u] = __float2half_rn(v[u]);
        tile[r][cs * 16 + u] = v[u];
        rs += v[u];
    }
    {
        size_t idx = (size_t)(bi + r) * NN + bj + cs * 16;
        *(uint4*)&g_Ah[idx]     = *(uint4*)&h[0];
        *(uint4*)&g_Ah[idx + 8] = *(uint4*)&h[8];
    }
    rs += __shfl_xor_sync(0xFFFFFFFFu, rs, 1);
    rs += __shfl_xor_sync(0xFFFFFFFFu, rs, 2);
    if (cs == 0) atomicAdd(&g_Din[bi + r], rs);

    __syncthreads();

    float csum = 0.f;
    #pragma unroll
    for (int u = 0; u < 16; u++) {
        float w = tile[cs * 16 + u][r];
        h[u] = __float2half_rn(w);
        csum += w;
    }
    {
        size_t idx = (size_t)(bj + r) * NN + bi + cs * 16;
        *(uint4*)&g_ATh[idx]     = *(uint4*)&h[0];
        *(uint4*)&g_ATh[idx + 8] = *(uint4*)&h[8];
    }
    csum += __shfl_xor_sync(0xFFFFFFFFu, csum, 1);
    csum += __shfl_xor_sync(0xFFFFFFFFu, csum, 2);
    if (cs == 0) atomicAdd(&g_Dout[bj + r], csum);
}

// ---------------- small fp32 GEMM (projections + dec) ----------------
// EPI 0 (proj): +bias[n], store TRANSPOSED fp16 at OH[n*NN + m]; blockIdx.z picks (A1,OH1)/(A2,OH2)
// EPI 1 (dec):  +bias[n], store row-major fp16 at OH1[m*EMB + n]
template<int EPI>
__global__ void __launch_bounds__(256)
sgemm_small(const float* __restrict__ A1, __half* __restrict__ OH1,
            const float* __restrict__ A2, __half* __restrict__ OH2,
            const float* __restrict__ B,
            int Kdim, const float* __restrict__ bias)
{
    constexpr int BM = 64, BN = 64, BK = 16;
    __shared__ float As[BK][BM + 4];
    __shared__ float Bs[BK][BN + 4];
    const float* A  = (blockIdx.z == 0) ? A1 : A2;
    __half*      OH = (blockIdx.z == 0) ? OH1 : OH2;
    const int t  = threadIdx.x;
    const int tx = t & 15, ty = t >> 4;
    const int m0 = blockIdx.y * BM, n0 = blockIdx.x * BN;

    float acc[4][4];
    #pragma unroll
    for (int i = 0; i < 4; i++)
        #pragma unroll
        for (int j = 0; j < 4; j++) acc[i][j] = 0.f;

    for (int k0 = 0; k0 < Kdim; k0 += BK) {
        {
            const int mm = t >> 2, kk = (t & 3) << 2;
            float4 v = *(const float4*)&A[(size_t)(m0 + mm) * Kdim + (k0 + kk)];
            As[kk + 0][mm] = v.x; As[kk + 1][mm] = v.y;
            As[kk + 2][mm] = v.z; As[kk + 3][mm] = v.w;
        }
        {
            const int nn = t >> 2, kk = (t & 3) << 2;
            float4 v = *(const float4*)&B[(size_t)(n0 + nn) * Kdim + (k0 + kk)];
            Bs[kk + 0][nn] = v.x; Bs[kk + 1][nn] = v.y;
            Bs[kk + 2][nn] = v.z; Bs[kk + 3][nn] = v.w;
        }
        __syncthreads();
        #pragma unroll
        for (int kk = 0; kk < BK; kk++) {
            float4 av = *(const float4*)&As[kk][ty << 2];
            float4 bv = *(const float4*)&Bs[kk][tx << 2];
            float a4[4] = {av.x, av.y, av.z, av.w};
            float b4[4] = {bv.x, bv.y, bv.z, bv.w};
            #pragma unroll
            for (int i = 0; i < 4; i++)
                #pragma unroll
                for (int j = 0; j < 4; j++) acc[i][j] += a4[i] * b4[j];
        }
        __syncthreads();
    }

    if (EPI == 0) {
        #pragma unroll
        for (int j = 0; j < 4; j++) {
            const int n = n0 + (tx << 2) + j;
            const float bn = bias[n];
            __align__(8) __half h[4];
            #pragma unroll
            for (int i = 0; i < 4; i++)
                h[i] = __float2half_rn(acc[i][j] + bn);
            *(uint2*)&OH[(size_t)n * NN + m0 + (ty << 2)] = *(uint2*)h;
        }
    } else {
        #pragma unroll
        for (int i = 0; i < 4; i++) {
            const int m = m0 + (ty << 2) + i;
            const int n = n0 + (tx << 2);
            __align__(8) __half h[4];
            #pragma unroll
            for (int j = 0; j < 4; j++)
                h[j] = __float2half_rn(acc[i][j] + bias[n + j]);
            *(uint2*)&OH[(size_t)m * EMB + n] = *(uint2*)h;
        }
    }
}

// ---------------- tensor-core fp16 GEMM: 128x64 tile, 4-stage ring, 1 sync/iter ----------------
// C(m,n) = sum_k A(m,k)*B(n,k); A m-major fp16, B n-major fp16.
// blockIdx.z selects pointer set 1 or 2 (fused dual-GEMM launch).
// EPI 1: v/deg[m], leaky_relu, store [K,N,D] remap; if OH!=null and layer==KL-1,
//        also store fp16 at OH[m*EMB + (n&127)].
// EPI 3: v * a*exp2(b*lg2(d)+c*d*log2e), d = dist[m*NN+n], store C[m*NN+n].
#define STG 15360u
#define NSTAGE 4
#define SMEM_BYTES (NSTAGE * 15360)

template<int EPI>
__global__ void __launch_bounds__(256)
mma_gemm(const __half* __restrict__ A1, const __half* __restrict__ B1,
         float* __restrict__ C1, const float* __restrict__ deg1, __half* __restrict__ OH1,
         const __half* __restrict__ A2, const __half* __restrict__ B2,
         float* __restrict__ C2, const float* __restrict__ deg2, __half* __restrict__ OH2,
         int lda, int ldb, int Kdim,
         const float* __restrict__ dist,
         const float* __restrict__ sa, const float* __restrict__ sb,
         const float* __restrict__ sc)
{
    extern __shared__ __align__(16) char smem[];
    const uint32_t sbase = smem_u32(smem);

    const __half* Ah  = (blockIdx.z == 0) ? A1 : A2;
    const __half* Bh  = (blockIdx.z == 0) ? B1 : B2;
    float*        C   = (blockIdx.z == 0) ? C1 : C2;
    const float*  deg = (blockIdx.z == 0) ? deg1 : deg2;
    __half*       OH  = (blockIdx.z == 0) ? OH1 : OH2;

    const int tid  = threadIdx.x;
    const int wid  = tid >> 5, lane = tid & 31;
    const int g    = lane >> 2, t4 = lane & 3;
    const int wm   = (wid >> 1) * 32;   // 4 warps in m (128)
    const int wn   = (wid & 1) * 32;    // 2 warps in n (64)
    const int m0   = blockIdx.y * 128;
    const int n0   = blockIdx.x * 64;

    const int arow0 = tid >> 2;
    const int aseg  = (tid & 3) * 16;
    const int asege = (tid & 3) * 8;

    const uint32_t aoff = (uint32_t)((wm + (lane & 7) + ((lane >> 3) & 1) * 8) * 80
                                     + (lane >> 4) * 16);
    const uint32_t boff = (uint32_t)((wn + (lane & 7) + ((lane >> 4) << 3)) * 80
                                     + ((lane >> 3) & 1) * 16);

    float acc[2][4][4];
    #pragma unroll
    for (int mi = 0; mi < 2; mi++)
        #pragma unroll
        for (int ni = 0; ni < 4; ni++)
            #pragma unroll
            for (int r = 0; r < 4; r++) acc[mi][ni][r] = 0.f;

    const int T = Kdim / 32;   // always >= 4 here (K=8192 -> 256, K=128 -> 4)

    auto issue = [&](int stage) {
        const int k0 = stage * 32;
        uint32_t sb = sbase + (uint32_t)(stage & (NSTAGE - 1)) * STG;
        #pragma unroll
        for (int it = 0; it < 2; it++) {
            int row = arow0 + it * 64;
            cp16(sb + row * 80 + aseg, &Ah[(size_t)(m0 + row) * lda + k0 + asege]);
        }
        cp16(sb + 10240 + arow0 * 80 + aseg,
             &Bh[(size_t)(n0 + arow0) * ldb + k0 + asege]);
        asm volatile("cp.async.commit_group;\n" ::: "memory");
    };

    issue(0);
    issue(1);
    issue(2);

    for (int it = 0; it < T; it++) {
        // complete stage `it`; leave newer stages in flight
        if (it + 3 <= T)
            asm volatile("cp.async.wait_group 2;\n" ::: "memory");
        else if (it + 2 == T)
            asm volatile("cp.async.wait_group 1;\n" ::: "memory");
        else
            asm volatile("cp.async.wait_group 0;\n" ::: "memory");
        __syncthreads();   // also guarantees everyone finished reading stage it-1

        const uint32_t sb = sbase + (uint32_t)(it & (NSTAGE - 1)) * STG;
        const uint32_t uA = sb + aoff;
        const uint32_t uB = sb + 10240 + boff;

        #pragma unroll
        for (int kk = 0; kk < 32; kk += 16) {
            const uint32_t kb = (uint32_t)(kk * 2);
            uint32_t ah[2][4], bh[4][2];
            #pragma unroll
            for (int mi = 0; mi < 2; mi++)
                ldsm4(ah[mi], uA + (uint32_t)(mi * 16 * 80) + kb);
            #pragma unroll
            for (int p = 0; p < 2; p++)
                ldsm4(&bh[2 * p][0], uB + (uint32_t)(p * 16 * 80) + kb);
            #pragma unroll
            for (int mi = 0; mi < 2; mi++)
                #pragma unroll
                for (int ni = 0; ni < 4; ni++)
                    mma16816(acc[mi][ni], ah[mi], bh[ni]);
        }

        // stage it+3 reuses the slot of stage it-1; safe after this iter's sync
        if (it + 3 < T) issue(it + 3);
    }

    // ---------------- epilogue ----------------
    float sa0 = 0.f, sb0 = 0.f, sc0 = 0.f;
    if (EPI == 3) { sa0 = *sa; sb0 = *sb; sc0 = *sc * 1.44269504f; }

    #pragma unroll
    for (int mi = 0; mi < 2; mi++) {
        const int mA = m0 + wm + mi * 16 + g;
        const int mB = mA + 8;
        float dA = 0.f, dB = 0.f;
        if (EPI == 1) { dA = deg[mA]; dB = deg[mB]; }
        #pragma unroll
        for (int ni = 0; ni < 4; ni++) {
            const int n = n0 + wn + ni * 8 + 2 * t4;
            float c0 = acc[mi][ni][0], c1 = acc[mi][ni][1];
            float c2 = acc[mi][ni][2], c3 = acc[mi][ni][3];
            if (EPI == 1) {
                c0 /= dA; c1 /= dA; c2 /= dB; c3 /= dB;
                c0 = (c0 > 0.f) ? c0 : 0.01f * c0;
                c1 = (c1 > 0.f) ? c1 : 0.01f * c1;
                c2 = (c2 > 0.f) ? c2 : 0.01f * c2;
                c3 = (c3 > 0.f) ? c3 : 0.01f * c3;
                const int e = n & 127;
                const size_t base = (size_t)(n >> 7) * ((size_t)NN * EMB) + e;
                *(float2*)&C[base + (size_t)mA * EMB] = make_float2(c0, c1);
                *(float2*)&C[base + (size_t)mB * EMB] = make_float2(c2, c3);
                if (OH != nullptr && (n >> 7) == KL - 1) {
                    __align__(4) __half h2[2];
                    h2[0] = __float2half_rn(c0);
                    h2[1] = __float2half_rn(c1);
                    *(uint32_t*)&OH[(size_t)mA * EMB + e] = *(uint32_t*)h2;
                    h2[0] = __float2half_rn(c2);
                    h2[1] = __float2half_rn(c3);
                    *(uint32_t*)&OH[(size_t)mB * EMB + e] = *(uint32_t*)h2;
                }
            } else { // EPI == 3
                float2 d0 = *(const float2*)&dist[(size_t)mA * NN + n];
                float2 d1 = *(const float2*)&dist[(size_t)mB * NN + n];
                float f0 = sa0 * fast_ex2(sb0 * fast_lg2(d0.x) + sc0 * d0.x);
                float f1 = sa0 * fast_ex2(sb0 * fast_lg2(d0.y) + sc0 * d0.y);
                float f2 = sa0 * fast_ex2(sb0 * fast_lg2(d1.x) + sc0 * d1.x);
                float f3 = sa0 * fast_ex2(sb0 * fast_lg2(d1.y) + sc0 * d1.y);
                *(float2*)&C[(size_t)mA * NN + n] = make_float2(c0 * f0, c1 * f1);
                *(float2*)&C[(size_t)mB * NN + n] = make_float2(c2 * f2, c3 * f3);
            }
        }
    }
}

// ---------------- launcher ----------------
extern "C" void kernel_launch(void* const* d_in, const int* in_sizes, int n_in,
                              void* d_out, int out_size)
{
    const float* p    = (const float*)d_in[0];
    const float* q    = (const float*)d_in[1];
    const float* A    = (const float*)d_in[2];
    const float* dist = (const float*)d_in[3];
    const float* Ws   = (const float*)d_in[4];
    const float* bs   = (const float*)d_in[5];
    const float* Wd   = (const float*)d_in[6];
    const float* bd   = (const float*)d_in[7];
    const float* a    = (const float*)d_in[8];
    const float* b    = (const float*)d_in[9];
    const float* c    = (const float*)d_in[10];

    float* out   = (float*)d_out;
    float* out_p = out;
    float* out_q = out   + (size_t)KL * NN * EMB;
    float* out_e = out_q + (size_t)KL * NN * EMB;

    __half *ah, *ath, *wph, *wqh, *dch, *qh;
    float *dout, *din;
    cudaGetSymbolAddress((void**)&ah,   g_Ah);
    cudaGetSymbolAddress((void**)&ath,  g_ATh);
    cudaGetSymbolAddress((void**)&wph,  g_Wph);
    cudaGetSymbolAddress((void**)&wqh,  g_Wqh);
    cudaGetSymbolAddress((void**)&dch,  g_dech);
    cudaGetSymbolAddress((void**)&qh,   g_qh);
    cudaGetSymbolAddress((void**)&dout, g_Dout);
    cudaGetSymbolAddress((void**)&din,  g_Din);

    cudaFuncSetAttribute(mma_gemm<1>, cudaFuncAttributeMaxDynamicSharedMemorySize, SMEM_BYTES);
    cudaFuncSetAttribute(mma_gemm<3>, cudaFuncAttributeMaxDynamicSharedMemorySize, SMEM_BYTES);

    // degrees + fp16 conversion + transpose in one pass over A
    zero_deg_kernel<<<NN / 256, 256>>>();
    prep_kernel<<<dim3(NN / 64, NN / 64), 256>>>(A);

    // both projections in ONE launch (z=0: p->Wph, z=1: q->Wqh), transposed fp16 [NKE][NN]
    sgemm_small<0><<<dim3(NKE / 64, NN / 64, 2), 256>>>(p, wph, q, wqh, Ws, EMB, bs);

    // both aggregations in ONE launch (z=0: p_k from A^T,Wp ; z=1: q_k from A,Wq + emit qh)
    mma_gemm<1><<<dim3(NKE / 64, NN / 128, 2), 256, SMEM_BYTES>>>(
        ath, wph, out_p, dout, nullptr,
        ah,  wqh, out_q, din,  qh,
        NN, NN, NN,
        nullptr, nullptr, nullptr, nullptr);

    // dec = p_k[-1] @ Wd^T + bd -> fp16
    const float* pk2 = out_p + (size_t)(KL - 1) * NN * EMB;
    sgemm_small<1><<<dim3(EMB / 64, NN / 64, 1), 256>>>(pk2, dch, nullptr, nullptr, Wd, EMB, bd);

    // e_ij = (dec @ q_k[-1]^T) * a * d^b * exp(c*d)   (single-pass fp16)
    mma_gemm<3><<<dim3(NN / 64, NN / 128, 1), 256, SMEM_BYTES>>>(
        dch, qh, out_e, nullptr, nullptr,
        nullptr, nullptr, nullptr, nullptr, nullptr,
        EMB, EMB, EMB,
        dist, a, b, c);
}

// round 15
// speedup vs baseline: 1.0807x; 1.0807x over previous
#include <cuda_runtime.h>
#include <cuda_fp16.h>
#include <stdint.h>
#include <math.h>

#define NN   8192
#define EMB  128
#define KL   3
#define NKE  (KL * EMB)   // 384

// ---------------- persistent scratch (no allocations allowed) ----------------
__device__ __align__(16) __half g_Ah [(size_t)NN * NN];   // A row-major fp16
__device__ __align__(16) __half g_ATh[(size_t)NN * NN];   // A^T fp16
__device__ __align__(16) __half g_Wph[(size_t)NKE * NN];  // Wp^T fp16
__device__ __align__(16) __half g_Wqh[(size_t)NKE * NN];  // Wq^T fp16
__device__ __align__(16) __half g_dech[(size_t)NN * EMB];
__device__ __align__(16) __half g_qh  [(size_t)NN * EMB];
__device__ float g_Dout[NN];
__device__ float g_Din [NN];

// ---------------- helpers ----------------
__device__ __forceinline__ void cp16(uint32_t dst_smem, const void* src) {
    asm volatile("cp.async.ca.shared.global [%0], [%1], 16;\n"
                 :: "r"(dst_smem), "l"(src));
}
__device__ __forceinline__ void mma16816(float* c, const uint32_t* a, const uint32_t* b) {
    asm volatile(
        "mma.sync.aligned.m16n8k16.row.col.f32.f16.f16.f32 "
        "{%0,%1,%2,%3}, {%4,%5,%6,%7}, {%8,%9}, {%0,%1,%2,%3};\n"
        : "+f"(c[0]), "+f"(c[1]), "+f"(c[2]), "+f"(c[3])
        : "r"(a[0]), "r"(a[1]), "r"(a[2]), "r"(a[3]), "r"(b[0]), "r"(b[1]));
}
__device__ __forceinline__ void ldsm4(uint32_t* r, uint32_t addr) {
    asm volatile("ldmatrix.sync.aligned.m8n8.x4.shared.b16 {%0,%1,%2,%3}, [%4];"
                 : "=r"(r[0]), "=r"(r[1]), "=r"(r[2]), "=r"(r[3]) : "r"(addr));
}
__device__ __forceinline__ uint32_t smem_u32(const void* p) {
    return (uint32_t)__cvta_generic_to_shared(p);
}
__device__ __forceinline__ float fast_lg2(float x) {
    float y; asm("lg2.approx.f32 %0, %1;" : "=f"(y) : "f"(x)); return y;
}
__device__ __forceinline__ float fast_ex2(float x) {
    float y; asm("ex2.approx.f32 %0, %1;" : "=f"(y) : "f"(x)); return y;
}

__global__ void zero_deg_kernel() {
    int i = blockIdx.x * blockDim.x + threadIdx.x;
    if (i < NN) { g_Dout[i] = 0.0f; g_Din[i] = 0.0f; }
}

// ---------------- prep: A -> fp16 (row-major + transposed) + degrees ----------------
__global__ void __launch_bounds__(256) prep_kernel(const float* __restrict__ A) {
    __shared__ float tile[64][65];
    const int bi = blockIdx.y * 64;
    const int bj = blockIdx.x * 64;
    const int tid = threadIdx.x;
    const int r  = tid >> 2;
    const int cs = tid & 3;

    const float* src = A + (size_t)(bi + r) * NN + bj + cs * 16;
    float v[16];
    #pragma unroll
    for (int u = 0; u < 4; u++) {
        float4 f = *(const float4*)(src + u * 4);
        v[u*4+0] = f.x; v[u*4+1] = f.y; v[u*4+2] = f.z; v[u*4+3] = f.w;
    }
    __align__(16) __half h[16];
    float rs = 0.f;
    #pragma unroll
    for (int u = 0; u < 16; u++) {
        h[u] = __float2half_rn(v[u]);
        tile[r][cs * 16 + u] = v[u];
        rs += v[u];
    }
    {
        size_t idx = (size_t)(bi + r) * NN + bj + cs * 16;
        *(uint4*)&g_Ah[idx]     = *(uint4*)&h[0];
        *(uint4*)&g_Ah[idx + 8] = *(uint4*)&h[8];
    }
    rs += __shfl_xor_sync(0xFFFFFFFFu, rs, 1);
    rs += __shfl_xor_sync(0xFFFFFFFFu, rs, 2);
    if (cs == 0) atomicAdd(&g_Din[bi + r], rs);

    __syncthreads();

    float csum = 0.f;
    #pragma unroll
    for (int u = 0; u < 16; u++) {
        float w = tile[cs * 16 + u][r];
        h[u] = __float2half_rn(w);
        csum += w;
    }
    {
        size_t idx = (size_t)(bj + r) * NN + bi + cs * 16;
        *(uint4*)&g_ATh[idx]     = *(uint4*)&h[0];
        *(uint4*)&g_ATh[idx + 8] = *(uint4*)&h[8];
    }
    csum += __shfl_xor_sync(0xFFFFFFFFu, csum, 1);
    csum += __shfl_xor_sync(0xFFFFFFFFu, csum, 2);
    if (cs == 0) atomicAdd(&g_Dout[bj + r], csum);
}

// ---------------- small fp32 GEMM (projections + dec) ----------------
// EPI 0 (proj): +bias[n], store TRANSPOSED fp16 at OH[n*NN + m]; blockIdx.z picks (A1,OH1)/(A2,OH2)
// EPI 1 (dec):  +bias[n], store row-major fp16 at OH1[m*EMB + n]
template<int EPI>
__global__ void __launch_bounds__(256)
sgemm_small(const float* __restrict__ A1, __half* __restrict__ OH1,
            const float* __restrict__ A2, __half* __restrict__ OH2,
            const float* __restrict__ B,
            int Kdim, const float* __restrict__ bias)
{
    constexpr int BM = 64, BN = 64, BK = 16;
    __shared__ float As[BK][BM + 4];
    __shared__ float Bs[BK][BN + 4];
    const float* A  = (blockIdx.z == 0) ? A1 : A2;
    __half*      OH = (blockIdx.z == 0) ? OH1 : OH2;
    const int t  = threadIdx.x;
    const int tx = t & 15, ty = t >> 4;
    const int m0 = blockIdx.y * BM, n0 = blockIdx.x * BN;

    float acc[4][4];
    #pragma unroll
    for (int i = 0; i < 4; i++)
        #pragma unroll
        for (int j = 0; j < 4; j++) acc[i][j] = 0.f;

    for (int k0 = 0; k0 < Kdim; k0 += BK) {
        {
            const int mm = t >> 2, kk = (t & 3) << 2;
            float4 v = *(const float4*)&A[(size_t)(m0 + mm) * Kdim + (k0 + kk)];
            As[kk + 0][mm] = v.x; As[kk + 1][mm] = v.y;
            As[kk + 2][mm] = v.z; As[kk + 3][mm] = v.w;
        }
        {
            const int nn = t >> 2, kk = (t & 3) << 2;
            float4 v = *(const float4*)&B[(size_t)(n0 + nn) * Kdim + (k0 + kk)];
            Bs[kk + 0][nn] = v.x; Bs[kk + 1][nn] = v.y;
            Bs[kk + 2][nn] = v.z; Bs[kk + 3][nn] = v.w;
        }
        __syncthreads();
        #pragma unroll
        for (int kk = 0; kk < BK; kk++) {
            float4 av = *(const float4*)&As[kk][ty << 2];
            float4 bv = *(const float4*)&Bs[kk][tx << 2];
            float a4[4] = {av.x, av.y, av.z, av.w};
            float b4[4] = {bv.x, bv.y, bv.z, bv.w};
            #pragma unroll
            for (int i = 0; i < 4; i++)
                #pragma unroll
                for (int j = 0; j < 4; j++) acc[i][j] += a4[i] * b4[j];
        }
        __syncthreads();
    }

    if (EPI == 0) {
        #pragma unroll
        for (int j = 0; j < 4; j++) {
            const int n = n0 + (tx << 2) + j;
            const float bn = bias[n];
            __align__(8) __half h[4];
            #pragma unroll
            for (int i = 0; i < 4; i++)
                h[i] = __float2half_rn(acc[i][j] + bn);
            *(uint2*)&OH[(size_t)n * NN + m0 + (ty << 2)] = *(uint2*)h;
        }
    } else {
        #pragma unroll
        for (int i = 0; i < 4; i++) {
            const int m = m0 + (ty << 2) + i;
            const int n = n0 + (tx << 2);
            __align__(8) __half h[4];
            #pragma unroll
            for (int j = 0; j < 4; j++)
                h[j] = __float2half_rn(acc[i][j] + bias[n + j]);
            *(uint2*)&OH[(size_t)m * EMB + n] = *(uint2*)h;
        }
    }
}

// ---------------- tensor-core fp16 GEMM: 128x128 tile, warp 32x64, 4-stage ring ----------------
// C(m,n) = sum_k A(m,k)*B(n,k); A m-major fp16, B n-major fp16.
// 8 warps: 4 in m x 2 in n, warp tile 32m x 64n. Prefetch depth 3 over 4 slots:
// stage it+3 reuses slot of stage it-1, protected by this iteration's __syncthreads.
// blockIdx.z selects pointer set 1 or 2 (fused dual-GEMM launch).
// EPI 1: v/deg[m], leaky_relu, store [K,N,D] remap; if OH!=null and layer==KL-1,
//        also store fp16 at OH[m*EMB + (n&127)].
// EPI 3: v * a*exp2(b*lg2(d)+c*d*log2e), d = dist[m*NN+n], store C[m*NN+n].
#define STG 20480u
#define NSTAGE 4
#define SMEM_BYTES (NSTAGE * 20480)

template<int EPI>
__global__ void __launch_bounds__(256)
mma_gemm(const __half* __restrict__ A1, const __half* __restrict__ B1,
         float* __restrict__ C1, const float* __restrict__ deg1, __half* __restrict__ OH1,
         const __half* __restrict__ A2, const __half* __restrict__ B2,
         float* __restrict__ C2, const float* __restrict__ deg2, __half* __restrict__ OH2,
         int lda, int ldb, int Kdim,
         const float* __restrict__ dist,
         const float* __restrict__ sa, const float* __restrict__ sb,
         const float* __restrict__ sc)
{
    extern __shared__ __align__(16) char smem[];
    const uint32_t sbase = smem_u32(smem);

    const __half* Ah  = (blockIdx.z == 0) ? A1 : A2;
    const __half* Bh  = (blockIdx.z == 0) ? B1 : B2;
    float*        C   = (blockIdx.z == 0) ? C1 : C2;
    const float*  deg = (blockIdx.z == 0) ? deg1 : deg2;
    __half*       OH  = (blockIdx.z == 0) ? OH1 : OH2;

    const int tid  = threadIdx.x;
    const int wid  = tid >> 5, lane = tid & 31;
    const int g    = lane >> 2, t4 = lane & 3;
    const int wm   = (wid >> 1) * 32;   // 4 warp-rows (128 m)
    const int wn   = (wid & 1) * 64;    // 2 warp-cols (128 n)
    const int m0   = blockIdx.y * 128;
    const int n0   = blockIdx.x * 128;

    // cp.async coords: 128 rows x 4 segs per operand, 2 cp16/thread/operand
    const int crow = tid >> 1;
    const int cseg = (tid & 1) * 2;

    // ldmatrix lane offsets (80B row stride, conflict-free)
    const uint32_t aoff = (uint32_t)((wm + (lane & 7) + ((lane >> 3) & 1) * 8) * 80
                                     + (lane >> 4) * 16);
    const uint32_t boff = (uint32_t)((wn + (lane & 7) + ((lane >> 4) << 3)) * 80
                                     + ((lane >> 3) & 1) * 16);

    float acc[2][8][4];
    #pragma unroll
    for (int mi = 0; mi < 2; mi++)
        #pragma unroll
        for (int ni = 0; ni < 8; ni++)
            #pragma unroll
            for (int r = 0; r < 4; r++) acc[mi][ni][r] = 0.f;

    const int T = Kdim / 32;

    auto issue = [&](int stage) {
        const int k0 = stage * 32;
        uint32_t sb = sbase + (uint32_t)(stage & (NSTAGE - 1)) * STG;
        #pragma unroll
        for (int u = 0; u < 2; u++) {
            int seg = cseg + u;
            cp16(sb + crow * 80 + seg * 16,
                 &Ah[(size_t)(m0 + crow) * lda + k0 + seg * 8]);
            cp16(sb + 10240 + crow * 80 + seg * 16,
                 &Bh[(size_t)(n0 + crow) * ldb + k0 + seg * 8]);
        }
        asm volatile("cp.async.commit_group;\n" ::: "memory");
    };

    issue(0);
    issue(1);
    issue(2);

    for (int it = 0; it < T; it++) {
        if (it + 3 <= T)
            asm volatile("cp.async.wait_group 2;\n" ::: "memory");
        else if (it + 2 == T)
            asm volatile("cp.async.wait_group 1;\n" ::: "memory");
        else
            asm volatile("cp.async.wait_group 0;\n" ::: "memory");
        __syncthreads();   // all warps done reading stage it-1; stage it data visible

        const uint32_t sb = sbase + (uint32_t)(it & (NSTAGE - 1)) * STG;
        const uint32_t uA = sb + aoff;
        const uint32_t uB = sb + 10240 + boff;

        #pragma unroll
        for (int kk = 0; kk < 32; kk += 16) {
            const uint32_t kb = (uint32_t)(kk * 2);
            uint32_t ah[2][4], bh[8][2];
            #pragma unroll
            for (int mi = 0; mi < 2; mi++)
                ldsm4(ah[mi], uA + (uint32_t)(mi * 16 * 80) + kb);
            #pragma unroll
            for (int p = 0; p < 4; p++)
                ldsm4(&bh[2 * p][0], uB + (uint32_t)(p * 16 * 80) + kb);
            #pragma unroll
            for (int mi = 0; mi < 2; mi++)
                #pragma unroll
                for (int ni = 0; ni < 8; ni++)
                    mma16816(acc[mi][ni], ah[mi], bh[ni]);
        }

        // stage it+3 reuses slot of stage it-1 — safe after this iter's sync
        if (it + 3 < T) issue(it + 3);
    }

    // ---------------- epilogue ----------------
    float sa0 = 0.f, sb0 = 0.f, sc0 = 0.f;
    if (EPI == 3) { sa0 = *sa; sb0 = *sb; sc0 = *sc * 1.44269504f; }

    #pragma unroll
    for (int mi = 0; mi < 2; mi++) {
        const int mA = m0 + wm + mi * 16 + g;
        const int mB = mA + 8;
        float dA = 0.f, dB = 0.f;
        if (EPI == 1) { dA = deg[mA]; dB = deg[mB]; }
        #pragma unroll
        for (int ni = 0; ni < 8; ni++) {
            const int n = n0 + wn + ni * 8 + 2 * t4;
            float c0 = acc[mi][ni][0], c1 = acc[mi][ni][1];
            float c2 = acc[mi][ni][2], c3 = acc[mi][ni][3];
            if (EPI == 1) {
                c0 /= dA; c1 /= dA; c2 /= dB; c3 /= dB;
                c0 = (c0 > 0.f) ? c0 : 0.01f * c0;
                c1 = (c1 > 0.f) ? c1 : 0.01f * c1;
                c2 = (c2 > 0.f) ? c2 : 0.01f * c2;
                c3 = (c3 > 0.f) ? c3 : 0.01f * c3;
                const int e = n & 127;
                const size_t base = (size_t)(n >> 7) * ((size_t)NN * EMB) + e;
                *(float2*)&C[base + (size_t)mA * EMB] = make_float2(c0, c1);
                *(float2*)&C[base + (size_t)mB * EMB] = make_float2(c2, c3);
                if (OH != nullptr && (n >> 7) == KL - 1) {
                    __align__(4) __half h2[2];
                    h2[0] = __float2half_rn(c0);
                    h2[1] = __float2half_rn(c1);
                    *(uint32_t*)&OH[(size_t)mA * EMB + e] = *(uint32_t*)h2;
                    h2[0] = __float2half_rn(c2);
                    h2[1] = __float2half_rn(c3);
                    *(uint32_t*)&OH[(size_t)mB * EMB + e] = *(uint32_t*)h2;
                }
            } else { // EPI == 3
                float2 d0 = *(const float2*)&dist[(size_t)mA * NN + n];
                float2 d1 = *(const float2*)&dist[(size_t)mB * NN + n];
                float f0 = sa0 * fast_ex2(sb0 * fast_lg2(d0.x) + sc0 * d0.x);
                float f1 = sa0 * fast_ex2(sb0 * fast_lg2(d0.y) + sc0 * d0.y);
                float f2 = sa0 * fast_ex2(sb0 * fast_lg2(d1.x) + sc0 * d1.x);
                float f3 = sa0 * fast_ex2(sb0 * fast_lg2(d1.y) + sc0 * d1.y);
                *(float2*)&C[(size_t)mA * NN + n] = make_float2(c0 * f0, c1 * f1);
                *(float2*)&C[(size_t)mB * NN + n] = make_float2(c2 * f2, c3 * f3);
            }
        }
    }
}

// ---------------- launcher ----------------
extern "C" void kernel_launch(void* const* d_in, const int* in_sizes, int n_in,
                              void* d_out, int out_size)
{
    const float* p    = (const float*)d_in[0];
    const float* q    = (const float*)d_in[1];
    const float* A    = (const float*)d_in[2];
    const float* dist = (const float*)d_in[3];
    const float* Ws   = (const float*)d_in[4];
    const float* bs   = (const float*)d_in[5];
    const float* Wd   = (const float*)d_in[6];
    const float* bd   = (const float*)d_in[7];
    const float* a    = (const float*)d_in[8];
    const float* b    = (const float*)d_in[9];
    const float* c    = (const float*)d_in[10];

    float* out   = (float*)d_out;
    float* out_p = out;
    float* out_q = out   + (size_t)KL * NN * EMB;
    float* out_e = out_q + (size_t)KL * NN * EMB;

    __half *ah, *ath, *wph, *wqh, *dch, *qh;
    float *dout, *din;
    cudaGetSymbolAddress((void**)&ah,   g_Ah);
    cudaGetSymbolAddress((void**)&ath,  g_ATh);
    cudaGetSymbolAddress((void**)&wph,  g_Wph);
    cudaGetSymbolAddress((void**)&wqh,  g_Wqh);
    cudaGetSymbolAddress((void**)&dch,  g_dech);
    cudaGetSymbolAddress((void**)&qh,   g_qh);
    cudaGetSymbolAddress((void**)&dout, g_Dout);
    cudaGetSymbolAddress((void**)&din,  g_Din);

    cudaFuncSetAttribute(mma_gemm<1>, cudaFuncAttributeMaxDynamicSharedMemorySize, SMEM_BYTES);
    cudaFuncSetAttribute(mma_gemm<3>, cudaFuncAttributeMaxDynamicSharedMemorySize, SMEM_BYTES);

    // degrees + fp16 conversion + transpose in one pass over A
    zero_deg_kernel<<<NN / 256, 256>>>();
    prep_kernel<<<dim3(NN / 64, NN / 64), 256>>>(A);

    // both projections in ONE launch (z=0: p->Wph, z=1: q->Wqh), transposed fp16 [NKE][NN]
    sgemm_small<0><<<dim3(NKE / 64, NN / 64, 2), 256>>>(p, wph, q, wqh, Ws, EMB, bs);

    // both aggregations in ONE launch (z=0: p_k from A^T,Wp ; z=1: q_k from A,Wq + emit qh)
    mma_gemm<1><<<dim3(NKE / 128, NN / 128, 2), 256, SMEM_BYTES>>>(
        ath, wph, out_p, dout, nullptr,
        ah,  wqh, out_q, din,  qh,
        NN, NN, NN,
        nullptr, nullptr, nullptr, nullptr);

    // dec = p_k[-1] @ Wd^T + bd -> fp16
    const float* pk2 = out_p + (size_t)(KL - 1) * NN * EMB;
    sgemm_small<1><<<dim3(EMB / 64, NN / 64, 1), 256>>>(pk2, dch, nullptr, nullptr, Wd, EMB, bd);

    // e_ij = (dec @ q_k[-1]^T) * a * d^b * exp(c*d)   (single-pass fp16)
    mma_gemm<3><<<dim3(NN / 128, NN / 128, 1), 256, SMEM_BYTES>>>(
        dch, qh, out_e, nullptr, nullptr,
        nullptr, nullptr, nullptr, nullptr, nullptr,
        EMB, EMB, EMB,
        dist, a, b, c);
}